// round 13
// baseline (speedup 1.0000x reference)
#include <cuda_runtime.h>
#include <cuda_fp16.h>
#include <cstdint>
#include <cstddef>

#define DI __device__ __forceinline__

// ---------------- problem constants ----------------
constexpr int BB = 8, CI = 512, CO = 512, KW = 5, LL = 4096;

// ---------------- GEMM tiling ----------------
constexpr int NIT = 40;                      // ic(8) outer x kw(5) inner
constexpr int ATILE = 16384;                 // A tile: 128 rows x 128B
constexpr int A_ST = 4;                      // A stages
constexpr int BSLAB = 136 * 128;             // 17408: B slab, 136 rows
constexpr int GEMM_SMEM = A_ST * ATILE + 2 * BSLAB;   // 100352

constexpr int BROWS = 4224;                  // g_Bx rows (33*128)

// ---------------- device scratch ----------------
__device__ __half g_Bx[(size_t)BB * 8 * BROWS * 64];
__device__ __half g_W[(size_t)KW * 4 * 8 * 8192];
__device__ float  g_avgp[BB * CI * 33];      // partial sums per (b,c,g)
__device__ float  g_h[BB * 4 * 128];
__device__ float  g_ka[BB * KW];
__device__ float  g_scale[BB * CO];

// ---------------- helpers ----------------
DI uint32_t smem_u32(const void* p) {
    uint32_t a;
    asm("{ .reg .u64 t; cvta.to.shared.u64 t, %1; cvt.u32.u64 %0, t; }" : "=r"(a) : "l"(p));
    return a;
}
DI uint32_t swz(uint32_t off) { return off ^ ((off >> 3) & 0x70); }
DI void cp16(uint32_t dst, const void* src) {
    asm volatile("cp.async.cg.shared.global [%0], [%1], 16;" :: "r"(dst), "l"(src) : "memory");
}
DI void cp_commit() { asm volatile("cp.async.commit_group;" ::: "memory"); }
template <int N> DI void cp_wait() { asm volatile("cp.async.wait_group %0;" :: "n"(N) : "memory"); }

DI void ldmx4(uint32_t& r0, uint32_t& r1, uint32_t& r2, uint32_t& r3, uint32_t a) {
    asm volatile("ldmatrix.sync.aligned.m8n8.x4.shared.b16 {%0,%1,%2,%3}, [%4];"
                 : "=r"(r0), "=r"(r1), "=r"(r2), "=r"(r3) : "r"(a));
}
DI void mma16816(float* c, const uint32_t* a, const uint32_t* b) {
    asm volatile(
        "mma.sync.aligned.m16n8k16.row.col.f32.f16.f16.f32 "
        "{%0,%1,%2,%3}, {%4,%5,%6,%7}, {%8,%9}, {%0,%1,%2,%3};"
        : "+f"(c[0]), "+f"(c[1]), "+f"(c[2]), "+f"(c[3])
        : "r"(a[0]), "r"(a[1]), "r"(a[2]), "r"(a[3]), "r"(b[0]), "r"(b[1]));
}
DI float dot4(float4 a, float4 b) {
    return a.x * b.x + a.y * b.y + a.z * b.z + a.w * b.w;
}

// ---------------- kernel 1: fused prepW (blocks 0-31) + prepB (blocks 32+) --------
__global__ void k_prep(const float* __restrict__ x, const float* __restrict__ w) {
    __shared__ float xs[128][65];        // used by prepB part only
    int tid = threadIdx.x;               // 256 threads

    if (blockIdx.x < 32) {
        int bx = blockIdx.x;
        int oT = bx >> 3, ic = bx & 7;
#pragma unroll 1
        for (int p = tid; p < 4096; p += 256) {   // 128 o-rows x 32 j2
            int ol = p >> 5, j2 = p & 31;
            int o = oT * 128 + ol;
            int i = ic * 64 + 2 * j2;
            const float* src = w + ((size_t)o * CI + i) * KW;
            float v[10];
#pragma unroll
            for (int q = 0; q < 10; ++q) v[q] = src[q];
            uint32_t off = swz((uint32_t)ol * 128 + j2 * 4);
#pragma unroll
            for (int k = 0; k < KW; ++k) {
                __half2 hv = __floats2half2_rn(v[k], v[5 + k]);
                char* tile = (char*)g_W + (size_t)((k * 4 + oT) * 8 + ic) * ATILE;
                *(uint32_t*)(tile + off) = *(uint32_t*)&hv;
            }
        }
        return;
    }

    int bx = blockIdx.x - 32;            // b*(8*33) + ic*33 + g
    int g = bx % 33;
    int ic = (bx / 33) & 7;
    int b = bx / (33 * 8);
    for (int e = tid; e < 64 * 64; e += 256) {
        int c = e >> 6, po = e & 63;
        int l = g * 128 - 2 + 2 * po;
        float2 v = make_float2(0.f, 0.f);
        if (l >= 0 && l < LL - 1)
            v = *(const float2*)(x + ((size_t)(b * CI + ic * 64 + c)) * LL + l);
        xs[2 * po][c] = v.x;
        xs[2 * po + 1][c] = v.y;
    }
    __syncthreads();

    {
        int c = tid >> 2, part = tid & 3;
        float s = 0.f;
#pragma unroll
        for (int q = 0; q < 32; ++q) s += xs[part * 32 + q][c];
        s += __shfl_xor_sync(0xFFFFFFFFu, s, 1);
        s += __shfl_xor_sync(0xFFFFFFFFu, s, 2);
        if (part == 0)
            g_avgp[((size_t)b * CI + ic * 64 + c) * 33 + g] = s;
    }

    char* base = (char*)g_Bx + ((size_t)(b * 8 + ic) * BROWS + (size_t)g * 128) * 128;
#pragma unroll
    for (int q = 0; q < 4; ++q) {
        int idx = tid + q * 256;
        int r = idx >> 3, j = idx & 7;
        uint32_t u[4];
#pragma unroll
        for (int p = 0; p < 4; ++p) {
            __half2 hv = __floats2half2_rn(xs[r][j * 8 + 2 * p], xs[r][j * 8 + 2 * p + 1]);
            u[p] = *(uint32_t*)&hv;
        }
        uint32_t off = (uint32_t)(j * 16) ^ (uint32_t)((r & 7) * 16);
        *(uint4*)(base + (size_t)r * 128 + off) = make_uint4(u[0], u[1], u[2], u[3]);
    }
}

// ---------------- kernel 2: attention layer 1 (64 blocks, 4 thr/row) --------------
__global__ void k_att1(
    const float* ka_w1, const float* ka_b1,
    const float* sa_w1, const float* sa_b1,
    const float* ia_w1, const float* ia_b1,
    const float* oa_w1, const float* oa_b1) {
    __shared__ float avgs[CI];
    int bx = blockIdx.x;
    int half = bx & 1, br = (bx >> 1) & 3, b = bx >> 3;
    int t = threadIdx.x;                 // 256 threads
    for (int c = t; c < CI; c += 256) {
        const float* p = g_avgp + ((size_t)b * CI + c) * 33;
        float s = 0.f;
#pragma unroll
        for (int gg = 0; gg < 33; ++gg) s += p[gg];
        avgs[c] = s * (1.f / (float)LL);
    }
    __syncthreads();

    const float* w1 = br == 0 ? ka_w1 : br == 1 ? sa_w1 : br == 2 ? ia_w1 : oa_w1;
    const float* b1 = br == 0 ? ka_b1 : br == 1 ? sa_b1 : br == 2 ? ia_b1 : oa_b1;
    int row = half * 64 + (t >> 2), q4 = t & 3;
    const float4* wr = (const float4*)(w1 + (size_t)row * CI) + q4 * 32;
    const float4* av = (const float4*)avgs + q4 * 32;
    float s = 0.f;
#pragma unroll 8
    for (int q = 0; q < 32; ++q) s += dot4(wr[q], av[q]);
    s += __shfl_xor_sync(0xFFFFFFFFu, s, 1);
    s += __shfl_xor_sync(0xFFFFFFFFu, s, 2);
    if (q4 == 0)
        g_h[(b * 4 + br) * 128 + row] = fmaxf(s + b1[row], 0.f);
}

// ---------------- kernel 3: attention layer 2 (64 blocks, 4 thr/output) -----------
__global__ void k_att2(
    const float* ka_w2, const float* ka_b2,
    const float* sa_w2, const float* sa_b2,
    const float* ia_w2, const float* ia_b2,
    const float* oa_w2, const float* oa_b2) {
    __shared__ float h[4 * 128];
    __shared__ float sav;
    int bx = blockIdx.x;
    int seg = bx & 7, b = bx >> 3;
    int t = threadIdx.x;                 // 256 threads
    h[t] = g_h[b * 512 + t];
    h[t + 256] = g_h[b * 512 + t + 256];
    __syncthreads();

    int o = seg * 64 + (t >> 2), q4 = t & 3;
    const float4* hoa = (const float4*)(h + 3 * 128) + q4 * 8;
    const float4* woa = (const float4*)(oa_w2 + (size_t)o * 128) + q4 * 8;
    const float4* hia = (const float4*)(h + 2 * 128) + q4 * 8;
    const float4* wia = (const float4*)(ia_w2 + (size_t)o * 128) + q4 * 8;
    float so = 0.f, si = 0.f;
#pragma unroll
    for (int q = 0; q < 8; ++q) {
        so += dot4(woa[q], hoa[q]);
        si += dot4(wia[q], hia[q]);
    }
    so += __shfl_xor_sync(0xFFFFFFFFu, so, 1);
    so += __shfl_xor_sync(0xFFFFFFFFu, so, 2);
    si += __shfl_xor_sync(0xFFFFFFFFu, si, 1);
    si += __shfl_xor_sync(0xFFFFFFFFu, si, 2);

    if (t < 32) {
        float ss = dot4(((const float4*)sa_w2)[t], ((const float4*)(h + 128))[t]);
#pragma unroll
        for (int off = 16; off; off >>= 1) ss += __shfl_xor_sync(0xFFFFFFFFu, ss, off);
        if (t == 0) sav = 1.f / (1.f + expf(-(ss + sa_b2[0])));
    }
    if (seg == 0 && t >= 64 && t < 64 + KW) {
        int kk = t - 64;
        const float4* wka = (const float4*)(ka_w2 + (size_t)kk * 128);
        const float4* hka = (const float4*)h;
        float sk = 0.f;
#pragma unroll 8
        for (int q = 0; q < 32; ++q) sk += dot4(wka[q], hka[q]);
        g_ka[b * KW + kk] = 1.f / (1.f + expf(-(sk + ka_b2[kk])));
    }
    __syncthreads();
    if (q4 == 0) {
        float oav = 1.f / (1.f + expf(-(so + oa_b2[o])));
        float iav = 1.f / (1.f + expf(-(si + ia_b2[o])));
        g_scale[b * CO + o] = sav * iav * oav;
    }
}

// ---------------- kernel 4: HMMA GEMM, B-slab reuse across kw ----------------------
__global__ void __launch_bounds__(128, 2)
k_gemm(const float* __restrict__ bias, float* __restrict__ out) {
    extern __shared__ char sm[];
    uint32_t sbase = smem_u32(sm);
    uint32_t bbase_s = sbase + A_ST * ATILE;
    int tid = threadIdx.x, lane = tid & 31, wid = tid >> 5;
    int bx = blockIdx.x;
    int oT = bx & 3, lT = (bx >> 2) & 31, b = bx >> 7;
    int wm = (wid & 1) * 64, wn = (wid >> 1) * 64;

    const char* wb = (const char*)g_W;
    const char* bb = (const char*)g_Bx;

    float kaf[KW];
#pragma unroll
    for (int k = 0; k < KW; ++k) kaf[k] = g_ka[b * KW + k];
    float ratio[KW];
    ratio[0] = kaf[KW - 1] / kaf[0];         // ic-boundary transition kw 4 -> 0
#pragma unroll
    for (int k = 1; k < KW; ++k) ratio[k] = kaf[k - 1] / kaf[k];

    // iteration it = ic*5 + kw (kw innermost)
    auto issueA = [&](int j) {
        int ic = j / 5, kw = j - ic * 5;
        const char* sA = wb + (size_t)((kw * 4 + oT) * 8 + ic) * ATILE;
        uint32_t dA = sbase + (j & 3) * ATILE;
#pragma unroll
        for (int q = 0; q < 8; ++q) {
            int c = (tid + q * 128) * 16;
            cp16(dA + c, sA + c);
        }
    };
    auto issueB = [&](int ic) {
        const char* sB = bb + ((size_t)(b * 8 + ic) * BROWS + (size_t)lT * 128) * 128;
        uint32_t dB = bbase_s + (ic & 1) * BSLAB;
        for (int c = tid; c < BSLAB / 16; c += 128)
            cp16(dB + c * 16, sB + c * 16);
    };

    float acc[4][8][4];
#pragma unroll
    for (int mi = 0; mi < 4; ++mi)
#pragma unroll
        for (int ni = 0; ni < 8; ++ni)
#pragma unroll
            for (int r = 0; r < 4; ++r) acc[mi][ni][r] = 0.f;

    int rowA = (lane & 7) + 8 * ((lane >> 3) & 1);
    int colA = (lane >> 4) * 16;
    uint32_t axor = (uint32_t)((lane & 7) << 4);
    int nOffB = ((lane >> 4) & 1) * 8 + (lane & 7);
    int colB = ((lane >> 3) & 1) * 16;

    issueA(0); issueB(0); cp_commit();       // G0
    issueA(1); issueB(1); cp_commit();       // G1
    issueA(2); cp_commit();                  // G2

#pragma unroll 1
    for (int it = 0; it < NIT; ++it) {
        cp_wait<2>();                        // group(it) complete
        __syncthreads();                     // all warps done with A stage (it-1)&3,
                                             // and (at kw==0) with B slab ic-1

        int j3 = it + 3;
        if (j3 < NIT) issueA(j3);
        if (it > 0 && it % 5 == 0) {
            int icn = it / 5 + 1;            // B(2)..B(7) at it=5,10,...,30
            if (icn < 8) issueB(icn);
        }
        cp_commit();

        int kw = it % 5;
        if (it > 0) {
            float r = ratio[kw];
#pragma unroll
            for (int mi = 0; mi < 4; ++mi)
#pragma unroll
                for (int ni = 0; ni < 8; ++ni)
#pragma unroll
                    for (int q = 0; q < 4; ++q) acc[mi][ni][q] *= r;
        }

        uint32_t bxor = (uint32_t)(((kw + (lane & 7)) & 7) << 4);
        uint32_t sA = sbase + (it & 3) * ATILE;
        uint32_t sB = bbase_s + ((it / 5) & 1) * BSLAB;
        uint32_t bRow0 = (uint32_t)(kw + wn + nOffB);  // slab NOT pre-shifted: +kw here
#pragma unroll
        for (int ks = 0; ks < 4; ++ks) {
            uint32_t afr[4][4], bfr[4][4];
#pragma unroll
            for (int mi = 0; mi < 4; ++mi)
                ldmx4(afr[mi][0], afr[mi][1], afr[mi][2], afr[mi][3],
                      (sA + (uint32_t)(wm + mi * 16 + rowA) * 128 + ks * 32 + colA) ^ axor);
#pragma unroll
            for (int nb = 0; nb < 4; ++nb)
                ldmx4(bfr[nb][0], bfr[nb][1], bfr[nb][2], bfr[nb][3],
                      (sB + (bRow0 + nb * 16) * 128 + ks * 32 + colB) ^ bxor);
#pragma unroll
            for (int mi = 0; mi < 4; ++mi)
#pragma unroll
                for (int nb = 0; nb < 4; ++nb) {
                    mma16816(acc[mi][nb * 2],     afr[mi], &bfr[nb][0]);
                    mma16816(acc[mi][nb * 2 + 1], afr[mi], &bfr[nb][2]);
                }
        }
    }

    // epilogue: (scale*ka[4])*acc + bias  (last iter has kw=4)
    int r0 = wm + (lane >> 2);
    float ka4 = kaf[KW - 1];
    float scb[4][2], bib[4][2];
#pragma unroll
    for (int mi = 0; mi < 4; ++mi) {
        int o0 = oT * 128 + r0 + mi * 16;
        scb[mi][0] = g_scale[b * CO + o0] * ka4;
        scb[mi][1] = g_scale[b * CO + o0 + 8] * ka4;
        bib[mi][0] = bias[o0];
        bib[mi][1] = bias[o0 + 8];
    }
    float* ob = out + ((size_t)(b * CO + oT * 128)) * LL + lT * 128;
#pragma unroll
    for (int mi = 0; mi < 4; ++mi) {
#pragma unroll
        for (int ni = 0; ni < 8; ++ni) {
            int rr = r0 + mi * 16;
            int cc = wn + (ni >> 1) * 16 + (ni & 1) * 8 + (lane & 3) * 2;
            float2 v0 = make_float2(scb[mi][0] * acc[mi][ni][0] + bib[mi][0],
                                    scb[mi][0] * acc[mi][ni][1] + bib[mi][0]);
            float2 v1 = make_float2(scb[mi][1] * acc[mi][ni][2] + bib[mi][1],
                                    scb[mi][1] * acc[mi][ni][3] + bib[mi][1]);
            *(float2*)(ob + (size_t)rr * LL + cc) = v0;
            *(float2*)(ob + (size_t)(rr + 8) * LL + cc) = v1;
        }
    }
}

// ---------------- launch ----------------
extern "C" void kernel_launch(void* const* d_in, const int* in_sizes, int n_in,
                              void* d_out, int out_size) {
    const float* x      = (const float*)d_in[0];
    const float* weight = (const float*)d_in[1];
    const float* bias   = (const float*)d_in[2];
    const float* ka_w1 = (const float*)d_in[3],  *ka_b1 = (const float*)d_in[4];
    const float* ka_w2 = (const float*)d_in[5],  *ka_b2 = (const float*)d_in[6];
    const float* sa_w1 = (const float*)d_in[7],  *sa_b1 = (const float*)d_in[8];
    const float* sa_w2 = (const float*)d_in[9],  *sa_b2 = (const float*)d_in[10];
    const float* ia_w1 = (const float*)d_in[11], *ia_b1 = (const float*)d_in[12];
    const float* ia_w2 = (const float*)d_in[13], *ia_b2 = (const float*)d_in[14];
    const float* oa_w1 = (const float*)d_in[15], *oa_b1 = (const float*)d_in[16];
    const float* oa_w2 = (const float*)d_in[17], *oa_b2 = (const float*)d_in[18];
    float* out = (float*)d_out;

    cudaFuncSetAttribute(k_gemm, cudaFuncAttributeMaxDynamicSharedMemorySize, GEMM_SMEM);

    k_prep<<<32 + BB * 8 * 33, 256>>>(x, weight);
    k_att1<<<BB * 8, 256>>>(ka_w1, ka_b1, sa_w1, sa_b1, ia_w1, ia_b1, oa_w1, oa_b1);
    k_att2<<<BB * 8, 256>>>(ka_w2, ka_b2, sa_w2, sa_b2, ia_w2, ia_b2, oa_w2, oa_b2);
    k_gemm<<<BB * 32 * 4, 128, GEMM_SMEM>>>(bias, out);
}

// round 14
// speedup vs baseline: 1.0737x; 1.0737x over previous
#include <cuda_runtime.h>
#include <cuda_fp16.h>
#include <cstdint>
#include <cstddef>

#define DI __device__ __forceinline__

// ---------------- problem constants ----------------
constexpr int BB = 8, CI = 512, CO = 512, KW = 5, LL = 4096;

// ---------------- GEMM tiling ----------------
constexpr int NIT = 40;                      // kw(5) outer x ic(8) inner
constexpr int TILE_B = 16384;                // 128 rows x 128B
constexpr int STAGE_B = 2 * TILE_B;          // 32 KB (A + B)
constexpr int NSTAGE = 3;
constexpr int GEMM_SMEM = NSTAGE * STAGE_B;  // 96 KB

constexpr int BROWS = 4224;                  // g_Bx rows (33*128)

// ---------------- device scratch ----------------
__device__ __half g_Bx[(size_t)BB * 8 * BROWS * 64];
__device__ __half g_W[(size_t)KW * 4 * 8 * 8192];
__device__ float  g_avgp[BB * CI * 33];      // partial sums per (b,c,g)
__device__ float  g_h[BB * 4 * 128];
__device__ float  g_ka[BB * KW];
__device__ float  g_scale[BB * CO];

// ---------------- helpers ----------------
DI uint32_t smem_u32(const void* p) {
    uint32_t a;
    asm("{ .reg .u64 t; cvta.to.shared.u64 t, %1; cvt.u32.u64 %0, t; }" : "=r"(a) : "l"(p));
    return a;
}
DI uint32_t swz(uint32_t off) { return off ^ ((off >> 3) & 0x70); }
DI void cp16(uint32_t dst, const void* src) {
    asm volatile("cp.async.cg.shared.global [%0], [%1], 16;" :: "r"(dst), "l"(src) : "memory");
}
DI void cp_commit() { asm volatile("cp.async.commit_group;" ::: "memory"); }
template <int N> DI void cp_wait() { asm volatile("cp.async.wait_group %0;" :: "n"(N) : "memory"); }

DI void ldmx4(uint32_t& r0, uint32_t& r1, uint32_t& r2, uint32_t& r3, uint32_t a) {
    asm volatile("ldmatrix.sync.aligned.m8n8.x4.shared.b16 {%0,%1,%2,%3}, [%4];"
                 : "=r"(r0), "=r"(r1), "=r"(r2), "=r"(r3) : "r"(a));
}
DI void mma16816(float* c, const uint32_t* a, const uint32_t* b) {
    asm volatile(
        "mma.sync.aligned.m16n8k16.row.col.f32.f16.f16.f32 "
        "{%0,%1,%2,%3}, {%4,%5,%6,%7}, {%8,%9}, {%0,%1,%2,%3};"
        : "+f"(c[0]), "+f"(c[1]), "+f"(c[2]), "+f"(c[3])
        : "r"(a[0]), "r"(a[1]), "r"(a[2]), "r"(a[3]), "r"(b[0]), "r"(b[1]));
}
DI float dot4(float4 a, float4 b) {
    return a.x * b.x + a.y * b.y + a.z * b.z + a.w * b.w;
}

// ---------------- kernel 1: fused prepW (blocks 0-31) + prepB (blocks 32+) --------
__global__ void k_prep(const float* __restrict__ x, const float* __restrict__ w) {
    __shared__ float xs[128][65];        // used by prepB part only
    int tid = threadIdx.x;               // 256 threads

    if (blockIdx.x < 32) {
        int bx = blockIdx.x;
        int oT = bx >> 3, ic = bx & 7;
#pragma unroll 1
        for (int p = tid; p < 4096; p += 256) {   // 128 o-rows x 32 j2
            int ol = p >> 5, j2 = p & 31;
            int o = oT * 128 + ol;
            int i = ic * 64 + 2 * j2;
            const float* src = w + ((size_t)o * CI + i) * KW;
            float v[10];
#pragma unroll
            for (int q = 0; q < 10; ++q) v[q] = src[q];
            uint32_t off = swz((uint32_t)ol * 128 + j2 * 4);
#pragma unroll
            for (int k = 0; k < KW; ++k) {
                __half2 hv = __floats2half2_rn(v[k], v[5 + k]);
                char* tile = (char*)g_W + (size_t)((k * 4 + oT) * 8 + ic) * TILE_B;
                *(uint32_t*)(tile + off) = *(uint32_t*)&hv;
            }
        }
        return;
    }

    int bx = blockIdx.x - 32;            // b*(8*33) + ic*33 + g
    int g = bx % 33;
    int ic = (bx / 33) & 7;
    int b = bx / (33 * 8);
    for (int e = tid; e < 64 * 64; e += 256) {
        int c = e >> 6, po = e & 63;
        int l = g * 128 - 2 + 2 * po;
        float2 v = make_float2(0.f, 0.f);
        if (l >= 0 && l < LL - 1)
            v = *(const float2*)(x + ((size_t)(b * CI + ic * 64 + c)) * LL + l);
        xs[2 * po][c] = v.x;
        xs[2 * po + 1][c] = v.y;
    }
    __syncthreads();

    {
        int c = tid >> 2, part = tid & 3;
        float s = 0.f;
#pragma unroll
        for (int q = 0; q < 32; ++q) s += xs[part * 32 + q][c];
        s += __shfl_xor_sync(0xFFFFFFFFu, s, 1);
        s += __shfl_xor_sync(0xFFFFFFFFu, s, 2);
        if (part == 0)
            g_avgp[((size_t)b * CI + ic * 64 + c) * 33 + g] = s;
    }

    char* base = (char*)g_Bx + ((size_t)(b * 8 + ic) * BROWS + (size_t)g * 128) * 128;
#pragma unroll
    for (int q = 0; q < 4; ++q) {
        int idx = tid + q * 256;
        int r = idx >> 3, j = idx & 7;
        uint32_t u[4];
#pragma unroll
        for (int p = 0; p < 4; ++p) {
            __half2 hv = __floats2half2_rn(xs[r][j * 8 + 2 * p], xs[r][j * 8 + 2 * p + 1]);
            u[p] = *(uint32_t*)&hv;
        }
        uint32_t off = (uint32_t)(j * 16) ^ (uint32_t)((r & 7) * 16);
        *(uint4*)(base + (size_t)r * 128 + off) = make_uint4(u[0], u[1], u[2], u[3]);
    }
}

// ---------------- kernel 2: attention layer 1 (64 blocks, 4 thr/row) --------------
__global__ void k_att1(
    const float* ka_w1, const float* ka_b1,
    const float* sa_w1, const float* sa_b1,
    const float* ia_w1, const float* ia_b1,
    const float* oa_w1, const float* oa_b1) {
    __shared__ float avgs[CI];
    int bx = blockIdx.x;
    int half = bx & 1, br = (bx >> 1) & 3, b = bx >> 3;
    int t = threadIdx.x;                 // 256 threads
    for (int c = t; c < CI; c += 256) {
        const float* p = g_avgp + ((size_t)b * CI + c) * 33;
        float s = 0.f;
#pragma unroll
        for (int gg = 0; gg < 33; ++gg) s += p[gg];
        avgs[c] = s * (1.f / (float)LL);
    }
    __syncthreads();

    const float* w1 = br == 0 ? ka_w1 : br == 1 ? sa_w1 : br == 2 ? ia_w1 : oa_w1;
    const float* b1 = br == 0 ? ka_b1 : br == 1 ? sa_b1 : br == 2 ? ia_b1 : oa_b1;
    int row = half * 64 + (t >> 2), q4 = t & 3;
    const float4* wr = (const float4*)(w1 + (size_t)row * CI) + q4 * 32;
    const float4* av = (const float4*)avgs + q4 * 32;
    float s = 0.f;
#pragma unroll 8
    for (int q = 0; q < 32; ++q) s += dot4(wr[q], av[q]);
    s += __shfl_xor_sync(0xFFFFFFFFu, s, 1);
    s += __shfl_xor_sync(0xFFFFFFFFu, s, 2);
    if (q4 == 0)
        g_h[(b * 4 + br) * 128 + row] = fmaxf(s + b1[row], 0.f);
}

// ---------------- kernel 3: attention layer 2 (64 blocks, 4 thr/output) -----------
__global__ void k_att2(
    const float* ka_w2, const float* ka_b2,
    const float* sa_w2, const float* sa_b2,
    const float* ia_w2, const float* ia_b2,
    const float* oa_w2, const float* oa_b2) {
    __shared__ float h[4 * 128];
    __shared__ float sav;
    int bx = blockIdx.x;
    int seg = bx & 7, b = bx >> 3;
    int t = threadIdx.x;                 // 256 threads
    h[t] = g_h[b * 512 + t];
    h[t + 256] = g_h[b * 512 + t + 256];
    __syncthreads();

    int o = seg * 64 + (t >> 2), q4 = t & 3;
    const float4* hoa = (const float4*)(h + 3 * 128) + q4 * 8;
    const float4* woa = (const float4*)(oa_w2 + (size_t)o * 128) + q4 * 8;
    const float4* hia = (const float4*)(h + 2 * 128) + q4 * 8;
    const float4* wia = (const float4*)(ia_w2 + (size_t)o * 128) + q4 * 8;
    float so = 0.f, si = 0.f;
#pragma unroll
    for (int q = 0; q < 8; ++q) {
        so += dot4(woa[q], hoa[q]);
        si += dot4(wia[q], hia[q]);
    }
    so += __shfl_xor_sync(0xFFFFFFFFu, so, 1);
    so += __shfl_xor_sync(0xFFFFFFFFu, so, 2);
    si += __shfl_xor_sync(0xFFFFFFFFu, si, 1);
    si += __shfl_xor_sync(0xFFFFFFFFu, si, 2);

    if (t < 32) {
        float ss = dot4(((const float4*)sa_w2)[t], ((const float4*)(h + 128))[t]);
#pragma unroll
        for (int off = 16; off; off >>= 1) ss += __shfl_xor_sync(0xFFFFFFFFu, ss, off);
        if (t == 0) sav = 1.f / (1.f + expf(-(ss + sa_b2[0])));
    }
    if (seg == 0 && t >= 64 && t < 64 + KW) {
        int kk = t - 64;
        const float4* wka = (const float4*)(ka_w2 + (size_t)kk * 128);
        const float4* hka = (const float4*)h;
        float sk = 0.f;
#pragma unroll 8
        for (int q = 0; q < 32; ++q) sk += dot4(wka[q], hka[q]);
        g_ka[b * KW + kk] = 1.f / (1.f + expf(-(sk + ka_b2[kk])));
    }
    __syncthreads();
    if (q4 == 0) {
        float oav = 1.f / (1.f + expf(-(so + oa_b2[o])));
        float iav = 1.f / (1.f + expf(-(si + ia_b2[o])));
        g_scale[b * CO + o] = sav * iav * oav;
    }
}

// ---------------- kernel 4: HMMA GEMM, m64n64 warps, ks-pipelined fragments --------
__global__ void __launch_bounds__(128, 2)
k_gemm(const float* __restrict__ bias, float* __restrict__ out) {
    extern __shared__ char sm[];
    uint32_t sbase = smem_u32(sm);
    int tid = threadIdx.x, lane = tid & 31, wid = tid >> 5;
    int bx = blockIdx.x;
    int oT = bx & 3, lT = (bx >> 2) & 31, b = bx >> 7;
    int wm = (wid & 1) * 64, wn = (wid >> 1) * 64;

    const char* wb = (const char*)g_W;
    const char* bb = (const char*)g_Bx;

    float kaf[KW];
#pragma unroll
    for (int k = 0; k < KW; ++k) kaf[k] = g_ka[b * KW + k];

    // iteration j: kw = j>>3 (outer), ic = j&7 (inner)
    auto issue = [&](int j, int s) {
        int kw = j >> 3, ic = j & 7;
        const char* sA = wb + (size_t)((kw * 4 + oT) * 8 + ic) * TILE_B;
        const char* sB = bb + ((size_t)(b * 8 + ic) * BROWS + (size_t)(lT * 128 + kw)) * 128;
        uint32_t dA = sbase + s * STAGE_B;
        uint32_t dB = dA + TILE_B;
#pragma unroll
        for (int q = 0; q < 8; ++q) {
            int c = (tid + q * 128) * 16;
            cp16(dA + c, sA + c);
        }
#pragma unroll
        for (int q = 0; q < 8; ++q) {
            int c = (tid + q * 128) * 16;
            cp16(dB + c, sB + c);
        }
    };

    float acc[4][8][4];
#pragma unroll
    for (int mi = 0; mi < 4; ++mi)
#pragma unroll
        for (int ni = 0; ni < 8; ++ni)
#pragma unroll
            for (int r = 0; r < 4; ++r) acc[mi][ni][r] = 0.f;

    int rowA = (lane & 7) + 8 * ((lane >> 3) & 1);
    int colA = (lane >> 4) * 16;
    uint32_t axor = (uint32_t)((lane & 7) << 4);
    int nOffB = ((lane >> 4) & 1) * 8 + (lane & 7);
    int colB = ((lane >> 3) & 1) * 16;

    issue(0, 0); cp_commit();
    issue(1, 1); cp_commit();

    uint32_t afr[2][4][4], bfr[2][4][4];

#pragma unroll 1
    for (int it = 0; it < NIT; ++it) {
        cp_wait<1>();
        __syncthreads();                        // all warps done reading stage (it-1)%3

        int kw = it >> 3;
        uint32_t bxor = (uint32_t)(((kw + (lane & 7)) & 7) << 4);
        uint32_t sA = sbase + (it % 3) * STAGE_B;
        uint32_t sB = sA + TILE_B;
        uint32_t bRow0 = (uint32_t)(wn + nOffB);

        // prefetch ks=0 fragments FIRST (head of critical path)
#pragma unroll
        for (int mi = 0; mi < 4; ++mi)
            ldmx4(afr[0][mi][0], afr[0][mi][1], afr[0][mi][2], afr[0][mi][3],
                  (sA + (uint32_t)(wm + mi * 16 + rowA) * 128 + colA) ^ axor);
#pragma unroll
        for (int nb = 0; nb < 4; ++nb)
            ldmx4(bfr[0][nb][0], bfr[0][nb][1], bfr[0][nb][2], bfr[0][nb][3],
                  (sB + (bRow0 + nb * 16) * 128 + colB) ^ bxor);

        // then the async fill for stage it+2 (has 2 iterations of slack)
        int j2 = it + 2;
        if (j2 < NIT) issue(j2, j2 % 3);
        cp_commit();

        // group boundary: rescale acc into units of ka[kw] (fma pipe, overlaps LDSM)
        if ((it & 7) == 0 && it > 0) {
            float r = kaf[kw - 1] / kaf[kw];
#pragma unroll
            for (int mi = 0; mi < 4; ++mi)
#pragma unroll
                for (int ni = 0; ni < 8; ++ni)
#pragma unroll
                    for (int q = 0; q < 4; ++q) acc[mi][ni][q] *= r;
        }

#pragma unroll
        for (int ks = 0; ks < 4; ++ks) {
            int cur = ks & 1, nxt = cur ^ 1;
            if (ks < 3) {
                // prefetch ks+1 fragments before the MMAs of ks
#pragma unroll
                for (int mi = 0; mi < 4; ++mi)
                    ldmx4(afr[nxt][mi][0], afr[nxt][mi][1], afr[nxt][mi][2], afr[nxt][mi][3],
                          (sA + (uint32_t)(wm + mi * 16 + rowA) * 128 + (ks + 1) * 32 + colA) ^ axor);
#pragma unroll
                for (int nb = 0; nb < 4; ++nb)
                    ldmx4(bfr[nxt][nb][0], bfr[nxt][nb][1], bfr[nxt][nb][2], bfr[nxt][nb][3],
                          (sB + (bRow0 + nb * 16) * 128 + (ks + 1) * 32 + colB) ^ bxor);
            }
#pragma unroll
            for (int mi = 0; mi < 4; ++mi)
#pragma unroll
                for (int nb = 0; nb < 4; ++nb) {
                    mma16816(acc[mi][nb * 2],     afr[cur][mi], &bfr[cur][nb][0]);
                    mma16816(acc[mi][nb * 2 + 1], afr[cur][mi], &bfr[cur][nb][2]);
                }
        }
    }

    // epilogue: (scale*ka[4])*acc + bias; ni -> col = wn + (ni>>1)*16 + (ni&1)*8
    int r0 = wm + (lane >> 2);
    float ka4 = kaf[KW - 1];
    float scb[4][2], bib[4][2];
#pragma unroll
    for (int mi = 0; mi < 4; ++mi) {
        int o0 = oT * 128 + r0 + mi * 16;
        scb[mi][0] = g_scale[b * CO + o0] * ka4;
        scb[mi][1] = g_scale[b * CO + o0 + 8] * ka4;
        bib[mi][0] = bias[o0];
        bib[mi][1] = bias[o0 + 8];
    }
    float* ob = out + ((size_t)(b * CO + oT * 128)) * LL + lT * 128;
#pragma unroll
    for (int mi = 0; mi < 4; ++mi) {
#pragma unroll
        for (int ni = 0; ni < 8; ++ni) {
            int rr = r0 + mi * 16;
            int cc = wn + (ni >> 1) * 16 + (ni & 1) * 8 + (lane & 3) * 2;
            float2 v0 = make_float2(scb[mi][0] * acc[mi][ni][0] + bib[mi][0],
                                    scb[mi][0] * acc[mi][ni][1] + bib[mi][0]);
            float2 v1 = make_float2(scb[mi][1] * acc[mi][ni][2] + bib[mi][1],
                                    scb[mi][1] * acc[mi][ni][3] + bib[mi][1]);
            *(float2*)(ob + (size_t)rr * LL + cc) = v0;
            *(float2*)(ob + (size_t)(rr + 8) * LL + cc) = v1;
        }
    }
}

// ---------------- launch ----------------
extern "C" void kernel_launch(void* const* d_in, const int* in_sizes, int n_in,
                              void* d_out, int out_size) {
    const float* x      = (const float*)d_in[0];
    const float* weight = (const float*)d_in[1];
    const float* bias   = (const float*)d_in[2];
    const float* ka_w1 = (const float*)d_in[3],  *ka_b1 = (const float*)d_in[4];
    const float* ka_w2 = (const float*)d_in[5],  *ka_b2 = (const float*)d_in[6];
    const float* sa_w1 = (const float*)d_in[7],  *sa_b1 = (const float*)d_in[8];
    const float* sa_w2 = (const float*)d_in[9],  *sa_b2 = (const float*)d_in[10];
    const float* ia_w1 = (const float*)d_in[11], *ia_b1 = (const float*)d_in[12];
    const float* ia_w2 = (const float*)d_in[13], *ia_b2 = (const float*)d_in[14];
    const float* oa_w1 = (const float*)d_in[15], *oa_b1 = (const float*)d_in[16];
    const float* oa_w2 = (const float*)d_in[17], *oa_b2 = (const float*)d_in[18];
    float* out = (float*)d_out;

    cudaFuncSetAttribute(k_gemm, cudaFuncAttributeMaxDynamicSharedMemorySize, GEMM_SMEM);

    k_prep<<<32 + BB * 8 * 33, 256>>>(x, weight);
    k_att1<<<BB * 8, 256>>>(ka_w1, ka_b1, sa_w1, sa_b1, ia_w1, ia_b1, oa_w1, oa_b1);
    k_att2<<<BB * 8, 256>>>(ka_w2, ka_b2, sa_w2, sa_b2, ia_w2, ia_b2, oa_w2, oa_b2);
    k_gemm<<<BB * 32 * 4, 128, GEMM_SMEM>>>(bias, out);
}